// round 8
// baseline (speedup 1.0000x reference)
#include <cuda_runtime.h>
#include <cuda_bf16.h>
#include <math.h>
#include <stdint.h>

// Problem dims
#define B_ 32
#define T_ 64
#define P_ 10
#define I_ 1024
#define H_ 1024
#define C_ 8
#define G4 4096
#define M_ (B_*T_*P_)     // 20480
#define NBLK 148

// Scratch (device globals; no allocation allowed)
__device__ float d_xwx[(size_t)T_*B_*P_*H_];   // 80 MB: x@Wx^T, layout [t][b][p][h]
__device__ float d_pA[16*B_*G4];               // h@Whh^T partials [ks][b][n]
__device__ float d_pC[16*B_*G4];               // emb@Wih^T partials [ks][b][n]
__device__ float d_scores[B_*P_];
__device__ float d_h[B_*H_];
__device__ float d_c[B_*H_];
__device__ int   d_ctrA[T_];
__device__ int   d_ctrC[T_];
__device__ unsigned int          d_barcnt;
__device__ volatile unsigned int d_bargen;

__device__ __forceinline__ float tanh_fast(float x) {
    float y; asm("tanh.approx.f32 %0, %1;" : "=f"(y) : "f"(x)); return y;
}
__device__ __forceinline__ float sigmoidf(float x) {
    return 1.0f / (1.0f + expf(-x));
}

// ---------------------------------------------------------------------------
// zero initial state + control state (runs every graph replay)
// ---------------------------------------------------------------------------
__global__ void zero_state() {
    int i0 = blockIdx.x * 256 + threadIdx.x;
    for (int i = i0; i < B_*H_; i += 128*256) { d_h[i] = 0.0f; d_c[i] = 0.0f; }
    if (i0 < B_*P_) d_scores[i0] = 0.0f;
    if (i0 < T_) { d_ctrA[i0] = 0; d_ctrC[i0] = 0; }
    if (i0 == 0) { d_barcnt = 0; d_bargen = 0; }
}

// ---------------------------------------------------------------------------
// sgemm_xwx (R5 FFMA version): xwx[t,b,p,h] = sum_i x[b,t,p,i]*Wx[h,i]
// ---------------------------------------------------------------------------
__global__ __launch_bounds__(256, 2) void sgemm_xwx(
    const float* __restrict__ A, const float* __restrict__ Bm)
{
    __shared__ float As[8][128];
    __shared__ float Bs[8][128];
    const int tid = threadIdx.x;
    const int m0 = blockIdx.y * 128;
    const int n0 = blockIdx.x * 128;
    const int tx = tid & 15;
    const int ty = tid >> 4;

    float acc[8][8];
#pragma unroll
    for (int i = 0; i < 8; i++)
#pragma unroll
        for (int j = 0; j < 8; j++) acc[i][j] = 0.0f;

    const int ar = tid >> 1;
    const int ac = (tid & 1) * 4;
    const float* Aptr = A  + (size_t)(m0 + ar) * I_ + ac;
    const float* Bptr = Bm + (size_t)(n0 + ar) * I_ + ac;

    float4 av = *(const float4*)(Aptr);
    float4 bv = *(const float4*)(Bptr);

    for (int kb = 0; kb < I_; kb += 8) {
        As[ac+0][ar] = av.x; As[ac+1][ar] = av.y; As[ac+2][ar] = av.z; As[ac+3][ar] = av.w;
        Bs[ac+0][ar] = bv.x; Bs[ac+1][ar] = bv.y; Bs[ac+2][ar] = bv.z; Bs[ac+3][ar] = bv.w;
        __syncthreads();
        float4 av_n = av, bv_n = bv;
        if (kb + 8 < I_) {
            av_n = *(const float4*)(Aptr + kb + 8);
            bv_n = *(const float4*)(Bptr + kb + 8);
        }
#pragma unroll
        for (int kk = 0; kk < 8; kk++) {
            float a_f[8], b_f[8];
            *(float4*)(a_f)     = *(const float4*)&As[kk][ty*8];
            *(float4*)(a_f + 4) = *(const float4*)&As[kk][ty*8 + 4];
            *(float4*)(b_f)     = *(const float4*)&Bs[kk][tx*8];
            *(float4*)(b_f + 4) = *(const float4*)&Bs[kk][tx*8 + 4];
#pragma unroll
            for (int i = 0; i < 8; i++)
#pragma unroll
                for (int j = 0; j < 8; j++)
                    acc[i][j] += a_f[i] * b_f[j];
        }
        __syncthreads();
        av = av_n; bv = bv_n;
    }

#pragma unroll
    for (int i = 0; i < 8; i++) {
        int r   = m0 + ty*8 + i;
        int b   = r / (T_*P_);
        int rem = r % (T_*P_);
        int t   = rem / P_;
        int p   = rem % P_;
        float* o = d_xwx + (size_t)((t*B_ + b)*P_ + p) * H_ + n0 + tx*8;
        *(float4*)(o)     = *(float4*)&acc[i][0];
        *(float4*)(o + 4) = *(float4*)&acc[i][4];
    }
}

// ---------------------------------------------------------------------------
// Persistent fused recurrence kernel.  148 blocks x 256 threads.
// ---------------------------------------------------------------------------
#define US 65   // smem row stride (odd -> conflict-free scalar LDS)

__global__ __launch_bounds__(256) void chain_persistent(
    const float* __restrict__ x,
    const float* __restrict__ Wh,  const float* __restrict__ Whh,
    const float* __restrict__ b_att, const float* __restrict__ v,
    const float* __restrict__ Wih,
    const float* __restrict__ bih, const float* __restrict__ bhh)
{
    __shared__ float u_s[32*US];    // [b][k] (or emb slice)
    __shared__ float w_s[128*US];   // [n][k]  (aliased as red[] in att epilogue)
    __shared__ float al_s[B_*P_];   // softmax alphas
    __shared__ int   s_u;

    const int tid = threadIdx.x;

    // grid barrier (CG-style: block-wide sync, master does fence+atomic+spin)
    auto gridbar = [&]() {
        __syncthreads();
        if (tid == 0) {
            __threadfence();
            unsigned int gen = d_bargen;
            if (atomicAdd(&d_barcnt, 1u) == NBLK - 1u) {
                d_barcnt = 0u;
                __threadfence();
                d_bargen = gen + 1u;
            } else {
                while (d_bargen == gen) { __nanosleep(64); }
            }
            __threadfence();
        }
        __syncthreads();
    };

    for (int t = 0; t < T_; t++) {
        // ================= PHASE A: h @ [Wh | Whh]^T ========================
        // units 0..31: attention (32n x 32b, full K, fused score epilogue)
        // units 32..543: gate rows (128n x 32b x 64k split-K partials)
        while (true) {
            if (tid == 0) s_u = atomicAdd(&d_ctrA[t], 1);
            __syncthreads();
            int u = s_u;
            if (u >= 544) break;

            if (u < 32) {
                // ---- attention unit ----
                const int n0   = u * 32;
                const int ksub = tid >> 6;          // 0..3
                const int grp  = tid & 63;
                const int n_loc = (grp >> 3) * 4;   // 0..28
                const int b0    = (grp & 7) * 4;    // 0..28
                float acc[4][4] = {};

                for (int kt = 0; kt < 16; kt++) {
                    __syncthreads();
                    int kb = kt * 64;
#pragma unroll
                    for (int r = 0; r < 2; r++) {
                        int l = tid + r*256;
                        int row = l >> 4, k4 = (l & 15) * 4;
                        float4 uv = __ldcg((const float4*)&d_h[row*H_ + kb + k4]);
                        u_s[row*US + k4+0] = uv.x; u_s[row*US + k4+1] = uv.y;
                        u_s[row*US + k4+2] = uv.z; u_s[row*US + k4+3] = uv.w;
                        float4 wv = __ldg((const float4*)&Wh[(size_t)(n0 + row)*H_ + kb + k4]);
                        w_s[row*US + k4+0] = wv.x; w_s[row*US + k4+1] = wv.y;
                        w_s[row*US + k4+2] = wv.z; w_s[row*US + k4+3] = wv.w;
                    }
                    __syncthreads();
#pragma unroll
                    for (int kl = 0; kl < 16; kl++) {
                        int k = (ksub << 4) + kl;
                        float wv[4], uv[4];
#pragma unroll
                        for (int i = 0; i < 4; i++) wv[i] = w_s[(n_loc+i)*US + k];
#pragma unroll
                        for (int j = 0; j < 4; j++) uv[j] = u_s[(b0+j)*US + k];
#pragma unroll
                        for (int i = 0; i < 4; i++)
#pragma unroll
                            for (int j = 0; j < 4; j++) acc[i][j] += wv[i]*uv[j];
                    }
                }
                __syncthreads();
                // reduce 4 ksub partials into red[n][b] (aliases w_s)
                float* red = w_s;   // 32 x 33
#pragma unroll
                for (int s = 0; s < 4; s++) {
                    if (ksub == s) {
#pragma unroll
                        for (int i = 0; i < 4; i++)
#pragma unroll
                            for (int j = 0; j < 4; j++) {
                                int idx = (n_loc+i)*33 + (b0+j);
                                if (s == 0) red[idx] = acc[i][j];
                                else        red[idx] += acc[i][j];
                            }
                    }
                    __syncthreads();
                }
                // fused score epilogue: 320 (b,p) items over 256 threads
                for (int l = tid; l < B_*P_; l += 256) {
                    int b = l & 31, p = l >> 5;
                    const float* xw = d_xwx + (size_t)((t*B_ + b)*P_ + p)*H_ + n0;
                    float s = 0.0f;
#pragma unroll
                    for (int n = 0; n < 32; n++) {
                        float e = xw[n] + red[n*33 + b] + __ldg(&b_att[n0+n]);
                        s += __ldg(&v[n0+n]) * tanh_fast(e);
                    }
                    atomicAdd(&d_scores[b*P_ + p], s);
                }
            } else {
                // ---- gate unit: Whh rows, split-K ----
                int g = u - 32;
                const int n0g = (g >> 4) * 128;
                const int ks  = g & 15;
                const int k0  = ks * 64;
                __syncthreads();
#pragma unroll
                for (int r = 0; r < 2; r++) {
                    int l = tid + r*256;
                    int row = l >> 4, k4 = (l & 15) * 4;
                    float4 uv = __ldcg((const float4*)&d_h[row*H_ + k0 + k4]);
                    u_s[row*US + k4+0] = uv.x; u_s[row*US + k4+1] = uv.y;
                    u_s[row*US + k4+2] = uv.z; u_s[row*US + k4+3] = uv.w;
                }
#pragma unroll
                for (int r = 0; r < 8; r++) {
                    int l = tid + r*256;
                    int row = l >> 4, k4 = (l & 15) * 4;
                    float4 wv = __ldg((const float4*)&Whh[(size_t)(n0g + row)*H_ + k0 + k4]);
                    w_s[row*US + k4+0] = wv.x; w_s[row*US + k4+1] = wv.y;
                    w_s[row*US + k4+2] = wv.z; w_s[row*US + k4+3] = wv.w;
                }
                __syncthreads();
                const int n_loc = (tid >> 3) * 4;   // 0..124
                const int b0    = (tid & 7) * 4;    // 0..28
                float acc[4][4] = {};
#pragma unroll 16
                for (int k = 0; k < 64; k++) {
                    float wv[4], uv[4];
#pragma unroll
                    for (int i = 0; i < 4; i++) wv[i] = w_s[(n_loc+i)*US + k];
#pragma unroll
                    for (int j = 0; j < 4; j++) uv[j] = u_s[(b0+j)*US + k];
#pragma unroll
                    for (int i = 0; i < 4; i++)
#pragma unroll
                        for (int j = 0; j < 4; j++) acc[i][j] += wv[i]*uv[j];
                }
#pragma unroll
                for (int j = 0; j < 4; j++) {
                    float4 o = make_float4(acc[0][j], acc[1][j], acc[2][j], acc[3][j]);
                    *(float4*)&d_pA[(size_t)(ks*B_ + b0 + j)*G4 + n0g + n_loc] = o;
                }
            }
        }
        gridbar();

        // ================= PHASE C: softmax+pool slice + emb @ Wih^T =======
        while (true) {
            if (tid == 0) s_u = atomicAdd(&d_ctrC[t], 1);
            __syncthreads();
            int u = s_u;
            if (u >= 512) break;

            const int n0g = (u >> 4) * 128;
            const int ks  = u & 15;
            const int k0  = ks * 64;
            __syncthreads();
            // softmax alphas (recomputed per unit; 10 floats per b)
            if (tid < B_) {
                int b = tid;
                float sc[P_];
#pragma unroll
                for (int p = 0; p < P_; p++) sc[p] = __ldcg(&d_scores[b*P_ + p]);
                float mx = sc[0];
#pragma unroll
                for (int p = 1; p < P_; p++) mx = fmaxf(mx, sc[p]);
                float ssum = 0.0f;
#pragma unroll
                for (int p = 0; p < P_; p++) { sc[p] = expf(sc[p]-mx); ssum += sc[p]; }
                float inv = 1.0f / ssum;
#pragma unroll
                for (int p = 0; p < P_; p++) al_s[b*P_ + p] = sc[p] * inv;
            }
            __syncthreads();
            // emb slice [32b x 64k] into u_s
            {
                int b = tid >> 3, kseg = (tid & 7) * 8;
                float e[8] = {};
#pragma unroll
                for (int p = 0; p < P_; p++) {
                    const float* xp = x + (size_t)((b*T_ + t)*P_ + p)*I_ + k0 + kseg;
                    float a = al_s[b*P_ + p];
                    float4 x0 = __ldg((const float4*)xp);
                    float4 x1 = __ldg((const float4*)(xp+4));
                    e[0]+=a*x0.x; e[1]+=a*x0.y; e[2]+=a*x0.z; e[3]+=a*x0.w;
                    e[4]+=a*x1.x; e[5]+=a*x1.y; e[6]+=a*x1.z; e[7]+=a*x1.w;
                }
#pragma unroll
                for (int q = 0; q < 8; q++) u_s[b*US + kseg + q] = e[q];
            }
            // w tile: Wih rows n0g..+127 at k0
#pragma unroll
            for (int r = 0; r < 8; r++) {
                int l = tid + r*256;
                int row = l >> 4, k4 = (l & 15) * 4;
                float4 wv = __ldg((const float4*)&Wih[(size_t)(n0g + row)*H_ + k0 + k4]);
                w_s[row*US + k4+0] = wv.x; w_s[row*US + k4+1] = wv.y;
                w_s[row*US + k4+2] = wv.z; w_s[row*US + k4+3] = wv.w;
            }
            __syncthreads();
            const int n_loc = (tid >> 3) * 4;
            const int b0    = (tid & 7) * 4;
            float acc[4][4] = {};
#pragma unroll 16
            for (int k = 0; k < 64; k++) {
                float wv[4], uv[4];
#pragma unroll
                for (int i = 0; i < 4; i++) wv[i] = w_s[(n_loc+i)*US + k];
#pragma unroll
                for (int j = 0; j < 4; j++) uv[j] = u_s[(b0+j)*US + k];
#pragma unroll
                for (int i = 0; i < 4; i++)
#pragma unroll
                    for (int j = 0; j < 4; j++) acc[i][j] += wv[i]*uv[j];
            }
#pragma unroll
            for (int j = 0; j < 4; j++) {
                float4 o = make_float4(acc[0][j], acc[1][j], acc[2][j], acc[3][j]);
                *(float4*)&d_pC[(size_t)(ks*B_ + b0 + j)*G4 + n0g + n_loc] = o;
            }
        }
        gridbar();

        // ================= PHASE CELL ======================================
        {
            int idx = blockIdx.x * 256 + tid;
            if (idx < B_*H_) {
                int b = idx >> 10, j = idx & 1023;
                float g4v[4];
#pragma unroll
                for (int g = 0; g < 4; g++) {
                    int n = g*1024 + j;
                    float s = __ldg(&bih[n]) + __ldg(&bhh[n]);
#pragma unroll
                    for (int ks = 0; ks < 16; ks++) {
                        s += __ldcg(&d_pA[(size_t)(ks*B_ + b)*G4 + n]);
                        s += __ldcg(&d_pC[(size_t)(ks*B_ + b)*G4 + n]);
                    }
                    g4v[g] = s;
                }
                float ig = sigmoidf(g4v[0]);
                float fg = sigmoidf(g4v[1]);
                float gg = tanhf(g4v[2]);
                float og = sigmoidf(g4v[3]);
                float cn = fg * __ldcg(&d_c[idx]) + ig * gg;
                d_c[idx] = cn;
                d_h[idx] = og * tanhf(cn);
            }
            // zero scores for next step: 320 items over 256 threads
            if (blockIdx.x == 0) {
                for (int l = tid; l < B_*P_; l += 256) d_scores[l] = 0.0f;
            }
        }
        gridbar();
    }
}

// ---------------------------------------------------------------------------
// Final FC
// ---------------------------------------------------------------------------
__global__ __launch_bounds__(256) void kfc(const float* __restrict__ Wfc,
                                           const float* __restrict__ bfc,
                                           float* __restrict__ out)
{
    int b = blockIdx.x;
    int w = threadIdx.x >> 5;
    int lane = threadIdx.x & 31;
    const float* h = &d_h[b*H_];
    float acc = 0.0f;
    for (int i = lane; i < H_; i += 32) acc += h[i] * Wfc[w*H_ + i];
#pragma unroll
    for (int o = 16; o; o >>= 1) acc += __shfl_xor_sync(0xffffffffu, acc, o);
    if (lane == 0) out[b*C_ + w] = acc + bfc[w];
}

// ---------------------------------------------------------------------------
extern "C" void kernel_launch(void* const* d_in, const int* in_sizes, int n_in,
                              void* d_out, int out_size)
{
    const float* x    = (const float*)d_in[0];
    const float* Wx   = (const float*)d_in[1];
    const float* Wh   = (const float*)d_in[2];
    const float* batt = (const float*)d_in[3];
    const float* v    = (const float*)d_in[4];
    const float* Wih  = (const float*)d_in[5];
    const float* Whh  = (const float*)d_in[6];
    const float* bih  = (const float*)d_in[7];
    const float* bhh  = (const float*)d_in[8];
    const float* Wfc  = (const float*)d_in[9];
    const float* bfc  = (const float*)d_in[10];
    float* out = (float*)d_out;

    zero_state<<<128, 256>>>();
    sgemm_xwx<<<dim3(H_/128, M_/128), 256>>>(x, Wx);
    chain_persistent<<<NBLK, 256>>>(x, Wh, Whh, batt, v, Wih, bih, bhh);
    kfc<<<32, 256>>>(Wfc, bfc, out);
}